// round 2
// baseline (speedup 1.0000x reference)
#include <cuda_runtime.h>
#include <cstdint>

#define N_NODES 50000
#define E_EDGES 800000
#define IN_F    128
#define HID_F   256
#define OUT_F   128

// ---------------- device scratch (no cudaMalloc allowed) ----------------
__device__ int   g_deg_out[N_NODES];
__device__ int   g_deg_in[N_NODES];
__device__ float g_out_isqrt[N_NODES];
__device__ float g_in_isqrt[N_NODES];
__device__ float g_m1[(size_t)N_NODES * IN_F];    // layer1 aggregated input
__device__ float g_t1[(size_t)N_NODES * HID_F];   // relu(m1*in_isqrt @ W1 + b1)
__device__ float g_g [(size_t)N_NODES * OUT_F];   // (t1*out_isqrt) @ W2

// ---------------- degree kernels ----------------
__global__ void k_deg_init() {
    int i = blockIdx.x * blockDim.x + threadIdx.x;
    if (i < N_NODES) { g_deg_out[i] = 1; g_deg_in[i] = 1; }  // self-loops
}

__global__ void k_deg_count(const int* __restrict__ ei) {
    int e = blockIdx.x * blockDim.x + threadIdx.x;
    if (e < E_EDGES) {
        atomicAdd(&g_deg_out[ei[e]], 1);
        atomicAdd(&g_deg_in[ei[E_EDGES + e]], 1);
    }
}

__global__ void k_isqrt() {
    int i = blockIdx.x * blockDim.x + threadIdx.x;
    if (i < N_NODES) {
        g_out_isqrt[i] = rsqrtf((float)g_deg_out[i]);
        g_in_isqrt[i]  = rsqrtf((float)g_deg_in[i]);
    }
}

// ---------------- init m1 with self-loop contribution: m1[v] = x[v]*out_isqrt[v] ----------------
__global__ void k_init_m1(const float* __restrict__ x) {
    int idx = blockIdx.x * blockDim.x + threadIdx.x;   // over N*32 float4s
    if (idx < N_NODES * (IN_F / 4)) {
        int v = idx >> 5;
        float s = g_out_isqrt[v];
        float4 a = reinterpret_cast<const float4*>(x)[idx];
        a.x *= s; a.y *= s; a.z *= s; a.w *= s;
        reinterpret_cast<float4*>(g_m1)[idx] = a;
    }
}

// ---------------- 128-wide edge aggregation: one warp per edge, red.v4 ----------------
template <bool SCALE_SRC>
__global__ void k_agg128(const int* __restrict__ src, const int* __restrict__ dst,
                         const float* __restrict__ feat, float* __restrict__ out) {
    int gt = blockIdx.x * blockDim.x + threadIdx.x;
    int e = gt >> 5;
    int lane = threadIdx.x & 31;
    if (e >= E_EDGES) return;
    int s = src[e];
    int d = dst[e];
    float4 a = reinterpret_cast<const float4*>(feat + (size_t)s * 128)[lane];
    if (SCALE_SRC) {
        float sc = g_out_isqrt[s];
        a.x *= sc; a.y *= sc; a.z *= sc; a.w *= sc;
    }
    float* o = out + (size_t)d * 128 + lane * 4;
    asm volatile("red.global.add.v4.f32 [%0], {%1, %2, %3, %4};"
                 :: "l"(o), "f"(a.x), "f"(a.y), "f"(a.z), "f"(a.w) : "memory");
}

// ---------------- tiled SGEMM with per-row pre-scale, optional bias/relu/dup-store ----------------
// C[M,Nc] = (rowscale[m] * A[m,:]) @ W[K,Nc]  (+bias) (relu)
template <bool RELU, bool BIAS, bool DUP>
__global__ __launch_bounds__(256)
void k_gemm_rowscale(const float* __restrict__ A, const float* __restrict__ W,
                     const float* __restrict__ rowscale, const float* __restrict__ bias,
                     float* __restrict__ C, float* __restrict__ C2,
                     int M, int K, int Nc) {
    constexpr int BM = 64, BN = 64, BK = 16;
    __shared__ float As[BK][BM];      // transposed A tile
    __shared__ float Ws[BK][BN];

    const int tid = threadIdx.x;
    const int tx = tid & 15;          // 0..15 -> N direction (x4)
    const int ty = tid >> 4;          // 0..15 -> M direction (x4)
    const int m0 = blockIdx.y * BM;
    const int n0 = blockIdx.x * BN;

    // A-load mapping: one float4 per thread
    const int ar = tid >> 2;             // 0..63 row within tile
    const int akc = (tid & 3) << 2;      // 0,4,8,12 k within tile
    // W-load mapping
    const int wkr = tid >> 4;            // 0..15
    const int wnc = (tid & 15) << 2;     // 0..60

    float acc[4][4] = {};

    for (int k0 = 0; k0 < K; k0 += BK) {
        // load A tile (scaled), transposed into As[k][m]
        {
            int arow = m0 + ar;
            float4 av = make_float4(0.f, 0.f, 0.f, 0.f);
            if (arow < M) {
                av = *reinterpret_cast<const float4*>(&A[(size_t)arow * K + k0 + akc]);
                float s = rowscale[arow];
                av.x *= s; av.y *= s; av.z *= s; av.w *= s;
            }
            As[akc + 0][ar] = av.x;
            As[akc + 1][ar] = av.y;
            As[akc + 2][ar] = av.z;
            As[akc + 3][ar] = av.w;
        }
        // load W tile
        *reinterpret_cast<float4*>(&Ws[wkr][wnc]) =
            *reinterpret_cast<const float4*>(&W[(size_t)(k0 + wkr) * Nc + n0 + wnc]);
        __syncthreads();

        #pragma unroll
        for (int k = 0; k < BK; k++) {
            float4 a4 = *reinterpret_cast<const float4*>(&As[k][ty << 2]);
            float4 b4 = *reinterpret_cast<const float4*>(&Ws[k][tx << 2]);
            float a[4] = {a4.x, a4.y, a4.z, a4.w};
            float b[4] = {b4.x, b4.y, b4.z, b4.w};
            #pragma unroll
            for (int i = 0; i < 4; i++)
                #pragma unroll
                for (int j = 0; j < 4; j++)
                    acc[i][j] = fmaf(a[i], b[j], acc[i][j]);
        }
        __syncthreads();
    }

    // epilogue
    const int row0 = m0 + (ty << 2);
    const int col = n0 + (tx << 2);
    float4 bv = make_float4(0.f, 0.f, 0.f, 0.f);
    if (BIAS) bv = *reinterpret_cast<const float4*>(&bias[col]);
    #pragma unroll
    for (int i = 0; i < 4; i++) {
        int row = row0 + i;
        if (row < M) {
            float4 c = make_float4(acc[i][0], acc[i][1], acc[i][2], acc[i][3]);
            if (BIAS) { c.x += bv.x; c.y += bv.y; c.z += bv.z; c.w += bv.w; }
            if (RELU) {
                c.x = fmaxf(c.x, 0.f); c.y = fmaxf(c.y, 0.f);
                c.z = fmaxf(c.z, 0.f); c.w = fmaxf(c.w, 0.f);
            }
            *reinterpret_cast<float4*>(&C[(size_t)row * Nc + col]) = c;
            if (DUP)
                *reinterpret_cast<float4*>(&C2[(size_t)row * Nc + col]) = c;
        }
    }
}

// ---------------- finalize: out = out * in_isqrt[row] + b2 ----------------
__global__ void k_finalize(float* __restrict__ out, const float* __restrict__ b2) {
    int idx = blockIdx.x * blockDim.x + threadIdx.x;   // over N*32 float4s
    if (idx < N_NODES * (OUT_F / 4)) {
        int v = idx >> 5;
        int f4 = idx & 31;
        float s = g_in_isqrt[v];
        float4 c = reinterpret_cast<float4*>(out)[idx];
        float4 b = reinterpret_cast<const float4*>(b2)[f4];
        c.x = fmaf(c.x, s, b.x);
        c.y = fmaf(c.y, s, b.y);
        c.z = fmaf(c.z, s, b.z);
        c.w = fmaf(c.w, s, b.w);
        reinterpret_cast<float4*>(out)[idx] = c;
    }
}

// ---------------- launch ----------------
extern "C" void kernel_launch(void* const* d_in, const int* in_sizes, int n_in,
                              void* d_out, int out_size) {
    const float* x  = (const float*)d_in[0];
    const int*   ei = (const int*)d_in[1];        // [2, E]: row0 = src, row1 = dst
    const float* W1 = (const float*)d_in[2];
    const float* b1 = (const float*)d_in[3];
    const float* W2 = (const float*)d_in[4];
    const float* b2 = (const float*)d_in[5];
    float* out = (float*)d_out;

    const int* src = ei;
    const int* dst = ei + E_EDGES;

    float* m1; cudaGetSymbolAddress((void**)&m1, g_m1);
    float* t1; cudaGetSymbolAddress((void**)&t1, g_t1);
    float* gg; cudaGetSymbolAddress((void**)&gg, g_g);
    float* in_isqrt;  cudaGetSymbolAddress((void**)&in_isqrt,  g_in_isqrt);
    float* out_isqrt; cudaGetSymbolAddress((void**)&out_isqrt, g_out_isqrt);

    // degrees
    k_deg_init<<<(N_NODES + 255) / 256, 256>>>();
    k_deg_count<<<(E_EDGES + 255) / 256, 256>>>(ei);
    k_isqrt<<<(N_NODES + 255) / 256, 256>>>();

    // layer 1: aggregate 128-dim scaled x
    k_init_m1<<<(N_NODES * 32 + 255) / 256, 256>>>(x);
    k_agg128<true><<<(E_EDGES * 32 + 255) / 256, 256>>>(src, dst, x, m1);

    // t1 = relu((m1 * in_isqrt) @ W1 + b1)   [N, 256]
    {
        dim3 grid(HID_F / 64, (N_NODES + 63) / 64);
        k_gemm_rowscale<true, true, false><<<grid, 256>>>(
            m1, W1, in_isqrt, b1, t1, nullptr, N_NODES, IN_F, HID_F);
    }

    // g = (t1 * out_isqrt) @ W2   [N, 128]; also self-loop-init d_out = g
    {
        dim3 grid(OUT_F / 64, (N_NODES + 63) / 64);
        k_gemm_rowscale<false, false, true><<<grid, 256>>>(
            t1, W2, out_isqrt, nullptr, gg, out, N_NODES, HID_F, OUT_F);
    }

    // layer 2 aggregate 128-dim g into d_out
    k_agg128<false><<<(E_EDGES * 32 + 255) / 256, 256>>>(src, dst, gg, out);

    // out = out * in_isqrt + b2
    k_finalize<<<(N_NODES * 32 + 255) / 256, 256>>>(out, b2);
}

// round 4
// speedup vs baseline: 1.8053x; 1.8053x over previous
#include <cuda_runtime.h>
#include <cuda_bf16.h>
#include <cstdint>

#define N_NODES 50000
#define E_EDGES 800000
#define IN_F    128
#define HID_F   256
#define OUT_F   128

__device__ int   g_deg_out[N_NODES];
__device__ int   g_deg_in[N_NODES];
__device__ float g_out_isqrt[N_NODES];
__device__ float g_in_isqrt[N_NODES];
__device__ float g_m1[(size_t)N_NODES * IN_F];
__device__ float g_t1[(size_t)N_NODES * HID_F];
__device__ float g_g [(size_t)N_NODES * OUT_F];
// weight images: W^T split hi/lo, row n, padded K (+8)
__device__ __nv_bfloat16 g_B1h[HID_F * (IN_F + 8)];
__device__ __nv_bfloat16 g_B1l[HID_F * (IN_F + 8)];
__device__ __nv_bfloat16 g_B2h[OUT_F * (HID_F + 8)];
__device__ __nv_bfloat16 g_B2l[OUT_F * (HID_F + 8)];

// ---------------- degrees ----------------
__global__ void k_deg_init() {
    int i = blockIdx.x * blockDim.x + threadIdx.x;
    if (i < N_NODES) { g_deg_out[i] = 1; g_deg_in[i] = 1; }
}
__global__ void k_deg_count(const int* __restrict__ ei) {
    int e = blockIdx.x * blockDim.x + threadIdx.x;
    if (e < E_EDGES) {
        atomicAdd(&g_deg_out[ei[e]], 1);
        atomicAdd(&g_deg_in[ei[E_EDGES + e]], 1);
    }
}
__global__ void k_isqrt() {
    int i = blockIdx.x * blockDim.x + threadIdx.x;
    if (i < N_NODES) {
        g_out_isqrt[i] = rsqrtf((float)g_deg_out[i]);
        g_in_isqrt[i]  = rsqrtf((float)g_deg_in[i]);
    }
}
__global__ void k_init_m1(const float* __restrict__ x) {
    int idx = blockIdx.x * blockDim.x + threadIdx.x;
    if (idx < N_NODES * 32) {
        float s = g_out_isqrt[idx >> 5];
        float4 a = reinterpret_cast<const float4*>(x)[idx];
        a.x *= s; a.y *= s; a.z *= s; a.w *= s;
        reinterpret_cast<float4*>(g_m1)[idx] = a;
    }
}

// ---------------- edge aggregation: warp/edge, red.v4 ----------------
template <bool SCALE_SRC>
__global__ void k_agg128(const int* __restrict__ src, const int* __restrict__ dst,
                         const float* __restrict__ feat, float* __restrict__ out) {
    int gt = blockIdx.x * blockDim.x + threadIdx.x;
    int e = gt >> 5, lane = threadIdx.x & 31;
    if (e >= E_EDGES) return;
    int s = src[e], d = dst[e];
    float4 a = reinterpret_cast<const float4*>(feat + (size_t)s * 128)[lane];
    if (SCALE_SRC) {
        float sc = g_out_isqrt[s];
        a.x *= sc; a.y *= sc; a.z *= sc; a.w *= sc;
    }
    float* o = out + (size_t)d * 128 + lane * 4;
    asm volatile("red.global.add.v4.f32 [%0], {%1,%2,%3,%4};"
                 :: "l"(o), "f"(a.x), "f"(a.y), "f"(a.z), "f"(a.w) : "memory");
}

// ---------------- weight prep: split + transpose, [n][K+8] ----------------
__global__ void k_prep_B(const float* __restrict__ W, __nv_bfloat16* __restrict__ Bh,
                         __nv_bfloat16* __restrict__ Bl, int K, int Nc) {
    int idx = blockIdx.x * blockDim.x + threadIdx.x;
    if (idx >= K * Nc) return;
    int n = idx / K, k = idx % K;
    float w = W[(size_t)k * Nc + n];
    __nv_bfloat16 h = __float2bfloat16(w);
    __nv_bfloat16 l = __float2bfloat16(w - __bfloat162float(h));
    Bh[(size_t)n * (K + 8) + k] = h;
    Bl[(size_t)n * (K + 8) + k] = l;
}

__device__ __forceinline__ void pk2(float a, float b, float s, uint32_t& uh, uint32_t& ul) {
    a *= s; b *= s;
    __nv_bfloat16 ha = __float2bfloat16(a), hb = __float2bfloat16(b);
    __nv_bfloat16 la = __float2bfloat16(a - __bfloat162float(ha));
    __nv_bfloat16 lb = __float2bfloat16(b - __bfloat162float(hb));
    uh = (uint32_t)__bfloat16_as_ushort(ha) | ((uint32_t)__bfloat16_as_ushort(hb) << 16);
    ul = (uint32_t)__bfloat16_as_ushort(la) | ((uint32_t)__bfloat16_as_ushort(lb) << 16);
}

// ---------------- mma.sync bf16 split-GEMM ----------------
// CTA tile 128x128, 8 warps (4M x 2N). 3 passes: AhBh + AlBh + AhBl.
// NC = total output cols (row stride of C); grid = (NC/128, ceil(M/128)).
template <int NC, int KSRC, bool L1MODE>
__global__ __launch_bounds__(256, 2)
void k_gemm_mma(const float* __restrict__ A, const __nv_bfloat16* __restrict__ Bh_img,
                const __nv_bfloat16* __restrict__ Bl_img, const float* __restrict__ prescale,
                const float* __restrict__ bias, const float* __restrict__ postscale,
                float* __restrict__ C, float* __restrict__ C2) {
    constexpr int KPAD = KSRC + 8;
    constexpr int NCHUNK = KSRC / 64;
    constexpr uint32_t ROWB = 144;          // smem row stride bytes (72 bf16)
    constexpr uint32_t SZ = 128 * ROWB;     // one tile image: 18432 B

    extern __shared__ char smem[];
    uint32_t sb;
    asm("{ .reg .u64 t; cvta.to.shared.u64 t, %1; cvt.u32.u64 %0, t; }" : "=r"(sb) : "l"(smem));
    const uint32_t sAh = sb, sAl = sb + SZ, sBh = sb + 2 * SZ, sBl = sb + 3 * SZ;

    const int tid = threadIdx.x, wid = tid >> 5, lane = tid & 31;
    const int wm = wid & 3, wn = wid >> 2;
    const int m0 = blockIdx.y * 128, n0 = blockIdx.x * 128;

    // A convert mapping
    const int r = tid >> 1, cb = (tid & 1) * 32;
    const int arow = m0 + r;
    float s = 1.0f;
    if (L1MODE && arow < N_NODES) s = prescale[arow];

    // ldmatrix per-thread base offsets
    const uint32_t a_off = (uint32_t)((wm * 32 + ((lane >> 3) & 1) * 8 + (lane & 7)) * ROWB
                                      + (lane >> 4) * 16);
    const uint32_t b_off = (uint32_t)((wn * 64 + ((lane >> 4) << 3) + (lane & 7)) * ROWB
                                      + ((lane >> 3) & 1) * 16);

    float acc[2][8][4] = {};

    for (int ch = 0; ch < NCHUNK; ch++) {
        if (ch) __syncthreads();
        // ---- A convert: 128x64 f32 -> Ah/Al bf16 ----
        {
            float4 v[8];
            if (arow < N_NODES) {
                const float4* ap = reinterpret_cast<const float4*>(
                    A + (size_t)arow * KSRC + ch * 64 + cb);
                #pragma unroll
                for (int j = 0; j < 8; j++) v[j] = ap[j];
            } else {
                #pragma unroll
                for (int j = 0; j < 8; j++) v[j] = make_float4(0.f, 0.f, 0.f, 0.f);
            }
            #pragma unroll
            for (int j = 0; j < 4; j++) {
                float4 p = v[2 * j], q = v[2 * j + 1];
                uint32_t h0, l0, h1, l1, h2, l2, h3, l3;
                pk2(p.x, p.y, s, h0, l0); pk2(p.z, p.w, s, h1, l1);
                pk2(q.x, q.y, s, h2, l2); pk2(q.z, q.w, s, h3, l3);
                uint32_t off = (uint32_t)(r * ROWB + cb * 2 + j * 16);
                asm volatile("st.shared.v4.b32 [%0], {%1,%2,%3,%4};"
                             :: "r"(sAh + off), "r"(h0), "r"(h1), "r"(h2), "r"(h3));
                asm volatile("st.shared.v4.b32 [%0], {%1,%2,%3,%4};"
                             :: "r"(sAl + off), "r"(l0), "r"(l1), "r"(l2), "r"(l3));
            }
        }
        // ---- B copy: rows n0..n0+127, cols [ch*64, ch*64+64) ----
        #pragma unroll
        for (int i = tid; i < 1024; i += 256) {
            int row = i >> 3, j = i & 7;
            const uint4* ph = reinterpret_cast<const uint4*>(
                Bh_img + (size_t)(n0 + row) * KPAD + ch * 64);
            const uint4* pl = reinterpret_cast<const uint4*>(
                Bl_img + (size_t)(n0 + row) * KPAD + ch * 64);
            uint4 u = ph[j];
            uint32_t off = (uint32_t)(row * ROWB + j * 16);
            asm volatile("st.shared.v4.b32 [%0], {%1,%2,%3,%4};"
                         :: "r"(sBh + off), "r"(u.x), "r"(u.y), "r"(u.z), "r"(u.w));
            u = pl[j];
            asm volatile("st.shared.v4.b32 [%0], {%1,%2,%3,%4};"
                         :: "r"(sBl + off), "r"(u.x), "r"(u.y), "r"(u.z), "r"(u.w));
        }
        __syncthreads();

        // ---- 3 passes x 4 k-steps of mma ----
        #pragma unroll
        for (int p = 0; p < 3; p++) {
            const uint32_t aB = (p == 1) ? sAl : sAh;
            const uint32_t bB = (p == 2) ? sBl : sBh;
            #pragma unroll
            for (int ks = 0; ks < 4; ks++) {
                uint32_t af[2][4], bf[4][4];
                #pragma unroll
                for (int mi = 0; mi < 2; mi++)
                    asm volatile(
                        "ldmatrix.sync.aligned.m8n8.x4.shared.b16 {%0,%1,%2,%3}, [%4];"
                        : "=r"(af[mi][0]), "=r"(af[mi][1]), "=r"(af[mi][2]), "=r"(af[mi][3])
                        : "r"(aB + a_off + (uint32_t)(mi * 16 * ROWB + ks * 32)));
                #pragma unroll
                for (int nj = 0; nj < 4; nj++)
                    asm volatile(
                        "ldmatrix.sync.aligned.m8n8.x4.shared.b16 {%0,%1,%2,%3}, [%4];"
                        : "=r"(bf[nj][0]), "=r"(bf[nj][1]), "=r"(bf[nj][2]), "=r"(bf[nj][3])
                        : "r"(bB + b_off + (uint32_t)(nj * 16 * ROWB + ks * 32)));
                #pragma unroll
                for (int mi = 0; mi < 2; mi++)
                    #pragma unroll
                    for (int nj = 0; nj < 8; nj++) {
                        float* d = acc[mi][nj];
                        uint32_t b0 = bf[nj >> 1][(nj & 1) * 2];
                        uint32_t b1 = bf[nj >> 1][(nj & 1) * 2 + 1];
                        asm volatile(
                            "mma.sync.aligned.m16n8k16.row.col.f32.bf16.bf16.f32 "
                            "{%0,%1,%2,%3}, {%4,%5,%6,%7}, {%8,%9}, {%0,%1,%2,%3};"
                            : "+f"(d[0]), "+f"(d[1]), "+f"(d[2]), "+f"(d[3])
                            : "r"(af[mi][0]), "r"(af[mi][1]), "r"(af[mi][2]), "r"(af[mi][3]),
                              "r"(b0), "r"(b1));
                    }
            }
        }
    }

    // ---- epilogue ----
    #pragma unroll
    for (int mi = 0; mi < 2; mi++) {
        int row0 = m0 + wm * 32 + mi * 16 + (lane >> 2);
        int row1 = row0 + 8;
        float os0 = 1.f, os1 = 1.f;
        if (L1MODE) {
            if (row0 < N_NODES) os0 = postscale[row0];
            if (row1 < N_NODES) os1 = postscale[row1];
        }
        #pragma unroll
        for (int nj = 0; nj < 8; nj++) {
            int col = n0 + wn * 64 + nj * 8 + (lane & 3) * 2;
            float* d = acc[mi][nj];
            float2 v0 = make_float2(d[0], d[1]);
            float2 v1 = make_float2(d[2], d[3]);
            if (L1MODE) {
                float2 bv = *reinterpret_cast<const float2*>(&bias[col]);
                v0.x = fmaxf(v0.x + bv.x, 0.f) * os0;
                v0.y = fmaxf(v0.y + bv.y, 0.f) * os0;
                v1.x = fmaxf(v1.x + bv.x, 0.f) * os1;
                v1.y = fmaxf(v1.y + bv.y, 0.f) * os1;
            }
            if (row0 < N_NODES) {
                *reinterpret_cast<float2*>(&C[(size_t)row0 * NC + col]) = v0;
                if (!L1MODE) *reinterpret_cast<float2*>(&C2[(size_t)row0 * NC + col]) = v0;
            }
            if (row1 < N_NODES) {
                *reinterpret_cast<float2*>(&C[(size_t)row1 * NC + col]) = v1;
                if (!L1MODE) *reinterpret_cast<float2*>(&C2[(size_t)row1 * NC + col]) = v1;
            }
        }
    }
}

// ---------------- finalize ----------------
__global__ void k_finalize(float* __restrict__ out, const float* __restrict__ b2) {
    int idx = blockIdx.x * blockDim.x + threadIdx.x;
    if (idx < N_NODES * 32) {
        float s = g_in_isqrt[idx >> 5];
        float4 c = reinterpret_cast<float4*>(out)[idx];
        float4 b = reinterpret_cast<const float4*>(b2)[idx & 31];
        c.x = fmaf(c.x, s, b.x); c.y = fmaf(c.y, s, b.y);
        c.z = fmaf(c.z, s, b.z); c.w = fmaf(c.w, s, b.w);
        reinterpret_cast<float4*>(out)[idx] = c;
    }
}

extern "C" void kernel_launch(void* const* d_in, const int* in_sizes, int n_in,
                              void* d_out, int out_size) {
    const float* x  = (const float*)d_in[0];
    const int*   ei = (const int*)d_in[1];
    const float* W1 = (const float*)d_in[2];
    const float* b1 = (const float*)d_in[3];
    const float* W2 = (const float*)d_in[4];
    const float* b2 = (const float*)d_in[5];
    float* out = (float*)d_out;
    const int* src = ei;
    const int* dst = ei + E_EDGES;

    float *m1, *t1, *gg, *in_isqrt, *out_isqrt;
    __nv_bfloat16 *b1h, *b1l, *b2h, *b2l;
    cudaGetSymbolAddress((void**)&m1, g_m1);
    cudaGetSymbolAddress((void**)&t1, g_t1);
    cudaGetSymbolAddress((void**)&gg, g_g);
    cudaGetSymbolAddress((void**)&in_isqrt, g_in_isqrt);
    cudaGetSymbolAddress((void**)&out_isqrt, g_out_isqrt);
    cudaGetSymbolAddress((void**)&b1h, g_B1h);
    cudaGetSymbolAddress((void**)&b1l, g_B1l);
    cudaGetSymbolAddress((void**)&b2h, g_B2h);
    cudaGetSymbolAddress((void**)&b2l, g_B2l);

    static bool attr_set = false;
    if (!attr_set) {
        cudaFuncSetAttribute(k_gemm_mma<HID_F, IN_F, true>,
                             cudaFuncAttributeMaxDynamicSharedMemorySize, 73728);
        cudaFuncSetAttribute(k_gemm_mma<OUT_F, HID_F, false>,
                             cudaFuncAttributeMaxDynamicSharedMemorySize, 73728);
        attr_set = true;
    }

    k_deg_init<<<(N_NODES + 255) / 256, 256>>>();
    k_deg_count<<<(E_EDGES + 255) / 256, 256>>>(ei);
    k_isqrt<<<(N_NODES + 255) / 256, 256>>>();

    k_prep_B<<<(IN_F * HID_F + 255) / 256, 256>>>(W1, b1h, b1l, IN_F, HID_F);
    k_prep_B<<<(HID_F * OUT_F + 255) / 256, 256>>>(W2, b2h, b2l, HID_F, OUT_F);

    k_init_m1<<<(N_NODES * 32 + 255) / 256, 256>>>(x);
    k_agg128<true><<<((size_t)E_EDGES * 32 + 255) / 256, 256>>>(src, dst, x, m1);

    // t1 = relu((m1*in_isqrt) @ W1 + b1) * out_isqrt   [N, 256]
    {
        dim3 grid(HID_F / 128, (N_NODES + 127) / 128);
        k_gemm_mma<HID_F, IN_F, true><<<grid, 256, 73728>>>(
            m1, b1h, b1l, in_isqrt, b1, out_isqrt, t1, nullptr);
    }
    // g = t1 @ W2 ; dup into out (self-loop term)   [N, 128]
    {
        dim3 grid(OUT_F / 128, (N_NODES + 127) / 128);
        k_gemm_mma<OUT_F, HID_F, false><<<grid, 256, 73728>>>(
            t1, b2h, b2l, nullptr, nullptr, nullptr, gg, out);
    }

    k_agg128<false><<<((size_t)E_EDGES * 32 + 255) / 256, 256>>>(src, dst, gg, out);
    k_finalize<<<(N_NODES * 32 + 255) / 256, 256>>>(out, b2);
}

// round 5
// speedup vs baseline: 2.6165x; 1.4493x over previous
#include <cuda_runtime.h>
#include <cuda_bf16.h>
#include <cstdint>

#define N_NODES 50000
#define E_EDGES 800000
#define IN_F    128
#define HID_F   256
#define OUT_F   128
#define NB_SCAN 196   // 196*256 = 50176 >= N_NODES

__device__ int   g_cnt_in[N_NODES];
__device__ int   g_cnt_out[N_NODES];
__device__ int   g_rowstart[N_NODES];
__device__ int   g_cur[N_NODES];
__device__ int   g_bsum[NB_SCAN];
__device__ int   g_boff[NB_SCAN];
__device__ int   g_csrc[E_EDGES];
__device__ float g_out_isqrt[N_NODES];
__device__ float g_in_isqrt[N_NODES];
__device__ float g_xs[(size_t)N_NODES * IN_F];    // x * out_isqrt
__device__ float g_m1[(size_t)N_NODES * IN_F];
__device__ float g_t1[(size_t)N_NODES * HID_F];
__device__ float g_g [(size_t)N_NODES * OUT_F];
// weight images: W^T split hi/lo, row n, padded K (+8)
__device__ __nv_bfloat16 g_B1h[HID_F * (IN_F + 8)];
__device__ __nv_bfloat16 g_B1l[HID_F * (IN_F + 8)];
__device__ __nv_bfloat16 g_B2h[OUT_F * (HID_F + 8)];
__device__ __nv_bfloat16 g_B2l[OUT_F * (HID_F + 8)];

// ---------------- CSR build ----------------
__global__ void k_hist_init() {
    int i = blockIdx.x * blockDim.x + threadIdx.x;
    if (i < N_NODES) { g_cnt_in[i] = 0; g_cnt_out[i] = 0; }
}
__global__ void k_hist(const int* __restrict__ ei) {
    int e = blockIdx.x * blockDim.x + threadIdx.x;
    if (e < E_EDGES) {
        atomicAdd(&g_cnt_out[ei[e]], 1);
        atomicAdd(&g_cnt_in[ei[E_EDGES + e]], 1);
    }
}
__global__ void k_isqrt() {
    int i = blockIdx.x * blockDim.x + threadIdx.x;
    if (i < N_NODES) {
        g_out_isqrt[i] = rsqrtf((float)(g_cnt_out[i] + 1));   // +1 self-loop
        g_in_isqrt[i]  = rsqrtf((float)(g_cnt_in[i] + 1));
    }
}
__global__ void k_scanA() {
    __shared__ int sm[256];
    int i = blockIdx.x * 256 + threadIdx.x;
    int v = (i < N_NODES) ? g_cnt_in[i] : 0;
    sm[threadIdx.x] = v;
    __syncthreads();
    #pragma unroll
    for (int off = 1; off < 256; off <<= 1) {
        int t = (threadIdx.x >= off) ? sm[threadIdx.x - off] : 0;
        __syncthreads();
        sm[threadIdx.x] += t;
        __syncthreads();
    }
    if (i < N_NODES) g_rowstart[i] = sm[threadIdx.x] - v;
    if (threadIdx.x == 255) g_bsum[blockIdx.x] = sm[255];
}
__global__ void k_scanB() {
    __shared__ int sm[256];
    int i = threadIdx.x;
    int v = (i < NB_SCAN) ? g_bsum[i] : 0;
    sm[i] = v;
    __syncthreads();
    #pragma unroll
    for (int off = 1; off < 256; off <<= 1) {
        int t = (i >= off) ? sm[i - off] : 0;
        __syncthreads();
        sm[i] += t;
        __syncthreads();
    }
    if (i < NB_SCAN) g_boff[i] = sm[i] - v;
}
__global__ void k_scanC() {
    int i = blockIdx.x * blockDim.x + threadIdx.x;
    if (i < N_NODES) {
        int rs = g_rowstart[i] + g_boff[i >> 8];
        g_rowstart[i] = rs;
        g_cur[i] = rs;
    }
}
__global__ void k_scatter(const int* __restrict__ ei) {
    int e = blockIdx.x * blockDim.x + threadIdx.x;
    if (e < E_EDGES) {
        int pos = atomicAdd(&g_cur[ei[E_EDGES + e]], 1);
        g_csrc[pos] = ei[e];
    }
}

// ---------------- xs = x * out_isqrt ----------------
__global__ void k_xs(const float* __restrict__ x) {
    int idx = blockIdx.x * blockDim.x + threadIdx.x;
    if (idx < N_NODES * 32) {
        float s = g_out_isqrt[idx >> 5];
        float4 a = reinterpret_cast<const float4*>(x)[idx];
        a.x *= s; a.y *= s; a.z *= s; a.w *= s;
        reinterpret_cast<float4*>(g_xs)[idx] = a;
    }
}

// ---------------- CSR gather-sum aggregation: warp per node ----------------
// L2MODE: out[v] = (feat[v] + sum feat[src]) * in_isqrt[v] + b2   (final output)
// else:   out[v] =  feat[v] + sum feat[src]                       (m1 for GEMM)
template <bool L2MODE>
__global__ __launch_bounds__(256)
void k_agg_csr(const float* __restrict__ feat, float* __restrict__ outp,
               const float* __restrict__ b2) {
    int w = (blockIdx.x * blockDim.x + threadIdx.x) >> 5;
    int lane = threadIdx.x & 31;
    if (w >= N_NODES) return;
    const float4* f4 = reinterpret_cast<const float4*>(feat);
    float4 acc = f4[(size_t)w * 32 + lane];          // self-loop term
    float4 acc2 = make_float4(0.f, 0.f, 0.f, 0.f);
    const int st = g_rowstart[w], cn = g_cnt_in[w];
    int j = 0;
    for (; j + 2 <= cn; j += 2) {
        int s0 = g_csrc[st + j], s1 = g_csrc[st + j + 1];
        float4 a0 = f4[(size_t)s0 * 32 + lane];
        float4 a1 = f4[(size_t)s1 * 32 + lane];
        acc.x += a0.x; acc.y += a0.y; acc.z += a0.z; acc.w += a0.w;
        acc2.x += a1.x; acc2.y += a1.y; acc2.z += a1.z; acc2.w += a1.w;
    }
    if (j < cn) {
        int s0 = g_csrc[st + j];
        float4 a0 = f4[(size_t)s0 * 32 + lane];
        acc.x += a0.x; acc.y += a0.y; acc.z += a0.z; acc.w += a0.w;
    }
    acc.x += acc2.x; acc.y += acc2.y; acc.z += acc2.z; acc.w += acc2.w;
    if (L2MODE) {
        float s = g_in_isqrt[w];
        float4 b = reinterpret_cast<const float4*>(b2)[lane];
        acc.x = fmaf(acc.x, s, b.x); acc.y = fmaf(acc.y, s, b.y);
        acc.z = fmaf(acc.z, s, b.z); acc.w = fmaf(acc.w, s, b.w);
    }
    reinterpret_cast<float4*>(outp)[(size_t)w * 32 + lane] = acc;
}

// ---------------- weight prep: split + transpose, [n][K+8] ----------------
__global__ void k_prep_B(const float* __restrict__ W, __nv_bfloat16* __restrict__ Bh,
                         __nv_bfloat16* __restrict__ Bl, int K, int Nc) {
    int idx = blockIdx.x * blockDim.x + threadIdx.x;
    if (idx >= K * Nc) return;
    int n = idx / K, k = idx % K;
    float w = W[(size_t)k * Nc + n];
    __nv_bfloat16 h = __float2bfloat16(w);
    __nv_bfloat16 l = __float2bfloat16(w - __bfloat162float(h));
    Bh[(size_t)n * (K + 8) + k] = h;
    Bl[(size_t)n * (K + 8) + k] = l;
}

__device__ __forceinline__ void pk2(float a, float b, float s, uint32_t& uh, uint32_t& ul) {
    a *= s; b *= s;
    __nv_bfloat16 ha = __float2bfloat16(a), hb = __float2bfloat16(b);
    __nv_bfloat16 la = __float2bfloat16(a - __bfloat162float(ha));
    __nv_bfloat16 lb = __float2bfloat16(b - __bfloat162float(hb));
    uh = (uint32_t)__bfloat16_as_ushort(ha) | ((uint32_t)__bfloat16_as_ushort(hb) << 16);
    ul = (uint32_t)__bfloat16_as_ushort(la) | ((uint32_t)__bfloat16_as_ushort(lb) << 16);
}

// ---------------- mma.sync bf16 split-GEMM (unchanged core from R4) ----------------
template <int NC, int KSRC, bool L1MODE>
__global__ __launch_bounds__(256, 2)
void k_gemm_mma(const float* __restrict__ A, const __nv_bfloat16* __restrict__ Bh_img,
                const __nv_bfloat16* __restrict__ Bl_img, const float* __restrict__ prescale,
                const float* __restrict__ bias, const float* __restrict__ postscale,
                float* __restrict__ C) {
    constexpr int KPAD = KSRC + 8;
    constexpr int NCHUNK = KSRC / 64;
    constexpr uint32_t ROWB = 144;
    constexpr uint32_t SZ = 128 * ROWB;

    extern __shared__ char smem[];
    uint32_t sb;
    asm("{ .reg .u64 t; cvta.to.shared.u64 t, %1; cvt.u32.u64 %0, t; }" : "=r"(sb) : "l"(smem));
    const uint32_t sAh = sb, sAl = sb + SZ, sBh = sb + 2 * SZ, sBl = sb + 3 * SZ;

    const int tid = threadIdx.x, wid = tid >> 5, lane = tid & 31;
    const int wm = wid & 3, wn = wid >> 2;
    const int m0 = blockIdx.y * 128, n0 = blockIdx.x * 128;

    const int r = tid >> 1, cb = (tid & 1) * 32;
    const int arow = m0 + r;
    float s = 1.0f;
    if (L1MODE && arow < N_NODES) s = prescale[arow];

    const uint32_t a_off = (uint32_t)((wm * 32 + ((lane >> 3) & 1) * 8 + (lane & 7)) * ROWB
                                      + (lane >> 4) * 16);
    const uint32_t b_off = (uint32_t)((wn * 64 + ((lane >> 4) << 3) + (lane & 7)) * ROWB
                                      + ((lane >> 3) & 1) * 16);

    float acc[2][8][4] = {};

    for (int ch = 0; ch < NCHUNK; ch++) {
        if (ch) __syncthreads();
        {
            float4 v[8];
            if (arow < N_NODES) {
                const float4* ap = reinterpret_cast<const float4*>(
                    A + (size_t)arow * KSRC + ch * 64 + cb);
                #pragma unroll
                for (int j = 0; j < 8; j++) v[j] = ap[j];
            } else {
                #pragma unroll
                for (int j = 0; j < 8; j++) v[j] = make_float4(0.f, 0.f, 0.f, 0.f);
            }
            #pragma unroll
            for (int j = 0; j < 4; j++) {
                float4 p = v[2 * j], q = v[2 * j + 1];
                uint32_t h0, l0, h1, l1, h2, l2, h3, l3;
                pk2(p.x, p.y, s, h0, l0); pk2(p.z, p.w, s, h1, l1);
                pk2(q.x, q.y, s, h2, l2); pk2(q.z, q.w, s, h3, l3);
                uint32_t off = (uint32_t)(r * ROWB + cb * 2 + j * 16);
                asm volatile("st.shared.v4.b32 [%0], {%1,%2,%3,%4};"
                             :: "r"(sAh + off), "r"(h0), "r"(h1), "r"(h2), "r"(h3));
                asm volatile("st.shared.v4.b32 [%0], {%1,%2,%3,%4};"
                             :: "r"(sAl + off), "r"(l0), "r"(l1), "r"(l2), "r"(l3));
            }
        }
        #pragma unroll
        for (int i = tid; i < 1024; i += 256) {
            int row = i >> 3, j = i & 7;
            const uint4* ph = reinterpret_cast<const uint4*>(
                Bh_img + (size_t)(n0 + row) * KPAD + ch * 64);
            const uint4* pl = reinterpret_cast<const uint4*>(
                Bl_img + (size_t)(n0 + row) * KPAD + ch * 64);
            uint4 u = ph[j];
            uint32_t off = (uint32_t)(row * ROWB + j * 16);
            asm volatile("st.shared.v4.b32 [%0], {%1,%2,%3,%4};"
                         :: "r"(sBh + off), "r"(u.x), "r"(u.y), "r"(u.z), "r"(u.w));
            u = pl[j];
            asm volatile("st.shared.v4.b32 [%0], {%1,%2,%3,%4};"
                         :: "r"(sBl + off), "r"(u.x), "r"(u.y), "r"(u.z), "r"(u.w));
        }
        __syncthreads();

        #pragma unroll
        for (int p = 0; p < 3; p++) {
            const uint32_t aB = (p == 1) ? sAl : sAh;
            const uint32_t bB = (p == 2) ? sBl : sBh;
            #pragma unroll
            for (int ks = 0; ks < 4; ks++) {
                uint32_t af[2][4], bf[4][4];
                #pragma unroll
                for (int mi = 0; mi < 2; mi++)
                    asm volatile(
                        "ldmatrix.sync.aligned.m8n8.x4.shared.b16 {%0,%1,%2,%3}, [%4];"
                        : "=r"(af[mi][0]), "=r"(af[mi][1]), "=r"(af[mi][2]), "=r"(af[mi][3])
                        : "r"(aB + a_off + (uint32_t)(mi * 16 * ROWB + ks * 32)));
                #pragma unroll
                for (int nj = 0; nj < 4; nj++)
                    asm volatile(
                        "ldmatrix.sync.aligned.m8n8.x4.shared.b16 {%0,%1,%2,%3}, [%4];"
                        : "=r"(bf[nj][0]), "=r"(bf[nj][1]), "=r"(bf[nj][2]), "=r"(bf[nj][3])
                        : "r"(bB + b_off + (uint32_t)(nj * 16 * ROWB + ks * 32)));
                #pragma unroll
                for (int mi = 0; mi < 2; mi++)
                    #pragma unroll
                    for (int nj = 0; nj < 8; nj++) {
                        float* d = acc[mi][nj];
                        uint32_t b0 = bf[nj >> 1][(nj & 1) * 2];
                        uint32_t b1 = bf[nj >> 1][(nj & 1) * 2 + 1];
                        asm volatile(
                            "mma.sync.aligned.m16n8k16.row.col.f32.bf16.bf16.f32 "
                            "{%0,%1,%2,%3}, {%4,%5,%6,%7}, {%8,%9}, {%0,%1,%2,%3};"
                            : "+f"(d[0]), "+f"(d[1]), "+f"(d[2]), "+f"(d[3])
                            : "r"(af[mi][0]), "r"(af[mi][1]), "r"(af[mi][2]), "r"(af[mi][3]),
                              "r"(b0), "r"(b1));
                    }
            }
        }
    }

    #pragma unroll
    for (int mi = 0; mi < 2; mi++) {
        int row0 = m0 + wm * 32 + mi * 16 + (lane >> 2);
        int row1 = row0 + 8;
        float os0 = 1.f, os1 = 1.f;
        if (L1MODE) {
            if (row0 < N_NODES) os0 = postscale[row0];
            if (row1 < N_NODES) os1 = postscale[row1];
        }
        #pragma unroll
        for (int nj = 0; nj < 8; nj++) {
            int col = n0 + wn * 64 + nj * 8 + (lane & 3) * 2;
            float* d = acc[mi][nj];
            float2 v0 = make_float2(d[0], d[1]);
            float2 v1 = make_float2(d[2], d[3]);
            if (L1MODE) {
                float2 bv = *reinterpret_cast<const float2*>(&bias[col]);
                v0.x = fmaxf(v0.x + bv.x, 0.f) * os0;
                v0.y = fmaxf(v0.y + bv.y, 0.f) * os0;
                v1.x = fmaxf(v1.x + bv.x, 0.f) * os1;
                v1.y = fmaxf(v1.y + bv.y, 0.f) * os1;
            }
            if (row0 < N_NODES)
                *reinterpret_cast<float2*>(&C[(size_t)row0 * NC + col]) = v0;
            if (row1 < N_NODES)
                *reinterpret_cast<float2*>(&C[(size_t)row1 * NC + col]) = v1;
        }
    }
}

extern "C" void kernel_launch(void* const* d_in, const int* in_sizes, int n_in,
                              void* d_out, int out_size) {
    const float* x  = (const float*)d_in[0];
    const int*   ei = (const int*)d_in[1];
    const float* W1 = (const float*)d_in[2];
    const float* b1 = (const float*)d_in[3];
    const float* W2 = (const float*)d_in[4];
    const float* b2 = (const float*)d_in[5];
    float* out = (float*)d_out;

    float *xs, *m1, *t1, *gg, *in_isqrt, *out_isqrt;
    __nv_bfloat16 *b1h, *b1l, *b2h, *b2l;
    cudaGetSymbolAddress((void**)&xs, g_xs);
    cudaGetSymbolAddress((void**)&m1, g_m1);
    cudaGetSymbolAddress((void**)&t1, g_t1);
    cudaGetSymbolAddress((void**)&gg, g_g);
    cudaGetSymbolAddress((void**)&in_isqrt, g_in_isqrt);
    cudaGetSymbolAddress((void**)&out_isqrt, g_out_isqrt);
    cudaGetSymbolAddress((void**)&b1h, g_B1h);
    cudaGetSymbolAddress((void**)&b1l, g_B1l);
    cudaGetSymbolAddress((void**)&b2h, g_B2h);
    cudaGetSymbolAddress((void**)&b2l, g_B2l);

    static bool attr_set = false;
    if (!attr_set) {
        cudaFuncSetAttribute(k_gemm_mma<HID_F, IN_F, true>,
                             cudaFuncAttributeMaxDynamicSharedMemorySize, 73728);
        cudaFuncSetAttribute(k_gemm_mma<OUT_F, HID_F, false>,
                             cudaFuncAttributeMaxDynamicSharedMemorySize, 73728);
        attr_set = true;
    }

    // ---- CSR build + degrees ----
    k_hist_init<<<(N_NODES + 255) / 256, 256>>>();
    k_hist<<<(E_EDGES + 255) / 256, 256>>>(ei);
    k_isqrt<<<(N_NODES + 255) / 256, 256>>>();
    k_scanA<<<NB_SCAN, 256>>>();
    k_scanB<<<1, 256>>>();
    k_scanC<<<(N_NODES + 255) / 256, 256>>>();
    k_scatter<<<(E_EDGES + 255) / 256, 256>>>(ei);

    // ---- weight prep (independent) ----
    k_prep_B<<<(IN_F * HID_F + 255) / 256, 256>>>(W1, b1h, b1l, IN_F, HID_F);
    k_prep_B<<<(HID_F * OUT_F + 255) / 256, 256>>>(W2, b2h, b2l, HID_F, OUT_F);

    // ---- layer 1 ----
    k_xs<<<(N_NODES * 32 + 255) / 256, 256>>>(x);
    k_agg_csr<false><<<(N_NODES * 32 + 255) / 256, 256>>>(xs, m1, nullptr);
    {
        dim3 grid(HID_F / 128, (N_NODES + 127) / 128);
        k_gemm_mma<HID_F, IN_F, true><<<grid, 256, 73728>>>(
            m1, b1h, b1l, in_isqrt, b1, out_isqrt, t1);
    }
    // ---- layer 2 ----
    {
        dim3 grid(OUT_F / 128, (N_NODES + 127) / 128);
        k_gemm_mma<OUT_F, HID_F, false><<<grid, 256, 73728>>>(
            t1, b2h, b2l, nullptr, nullptr, nullptr, gg);
    }
    k_agg_csr<true><<<(N_NODES * 32 + 255) / 256, 256>>>(gg, out, b2);
}

// round 6
// speedup vs baseline: 3.2564x; 1.2446x over previous
#include <cuda_runtime.h>
#include <cuda_bf16.h>
#include <cstdint>

#define N_NODES 50000
#define E_EDGES 800000
#define IN_F    128
#define HID_F   256
#define OUT_F   128
#define NB_SCAN 196   // 196*256 = 50176 >= N_NODES

__device__ int   g_cnt_in[N_NODES];
__device__ int   g_cnt_out[N_NODES];
__device__ int   g_rowstart[N_NODES];
__device__ int   g_cur[N_NODES];
__device__ int   g_bsum[NB_SCAN];
__device__ int   g_boff[NB_SCAN];
__device__ int   g_csrc[E_EDGES];
__device__ float g_out_isqrt[N_NODES];
__device__ float g_in_isqrt[N_NODES];
__device__ float g_m1[(size_t)N_NODES * IN_F];
__device__ float g_t1[(size_t)N_NODES * HID_F];
__device__ float g_g [(size_t)N_NODES * OUT_F];
// weight images: W^T split hi/lo, row n, padded K (+8)
__device__ __nv_bfloat16 g_B1h[HID_F * (IN_F + 8)];
__device__ __nv_bfloat16 g_B1l[HID_F * (IN_F + 8)];
__device__ __nv_bfloat16 g_B2h[OUT_F * (HID_F + 8)];
__device__ __nv_bfloat16 g_B2l[OUT_F * (HID_F + 8)];

// ---------------- CSR build ----------------
__global__ void k_hist_init() {
    int i = blockIdx.x * blockDim.x + threadIdx.x;
    if (i < N_NODES) { g_cnt_in[i] = 0; g_cnt_out[i] = 0; }
}
__global__ void k_hist(const int* __restrict__ ei) {
    int e = blockIdx.x * blockDim.x + threadIdx.x;
    if (e < E_EDGES) {
        atomicAdd(&g_cnt_out[ei[e]], 1);
        atomicAdd(&g_cnt_in[ei[E_EDGES + e]], 1);
    }
}
__global__ void k_scanA() {
    __shared__ int sm[256];
    int i = blockIdx.x * 256 + threadIdx.x;
    int v = (i < N_NODES) ? g_cnt_in[i] : 0;
    sm[threadIdx.x] = v;
    __syncthreads();
    #pragma unroll
    for (int off = 1; off < 256; off <<= 1) {
        int t = (threadIdx.x >= off) ? sm[threadIdx.x - off] : 0;
        __syncthreads();
        sm[threadIdx.x] += t;
        __syncthreads();
    }
    if (i < N_NODES) g_rowstart[i] = sm[threadIdx.x] - v;
    if (threadIdx.x == 255) g_bsum[blockIdx.x] = sm[255];
}
__global__ void k_scanB() {
    __shared__ int sm[256];
    int i = threadIdx.x;
    int v = (i < NB_SCAN) ? g_bsum[i] : 0;
    sm[i] = v;
    __syncthreads();
    #pragma unroll
    for (int off = 1; off < 256; off <<= 1) {
        int t = (i >= off) ? sm[i - off] : 0;
        __syncthreads();
        sm[i] += t;
        __syncthreads();
    }
    if (i < NB_SCAN) g_boff[i] = sm[i] - v;
}
__global__ void k_scanC() {   // finalize rowstarts + compute isqrt (fused)
    int i = blockIdx.x * blockDim.x + threadIdx.x;
    if (i < N_NODES) {
        int rs = g_rowstart[i] + g_boff[i >> 8];
        g_rowstart[i] = rs;
        g_cur[i] = rs;
        g_out_isqrt[i] = rsqrtf((float)(g_cnt_out[i] + 1));
        g_in_isqrt[i]  = rsqrtf((float)(g_cnt_in[i] + 1));
    }
}
__global__ void k_scatter(const int* __restrict__ ei) {
    int e = blockIdx.x * blockDim.x + threadIdx.x;
    if (e < E_EDGES) {
        int pos = atomicAdd(&g_cur[ei[E_EDGES + e]], 1);
        g_csrc[pos] = ei[e];
    }
}

// ---------------- CSR gather-sum aggregation: warp per node ----------------
// SCALE_SRC: every contributing row (incl. self) is scaled by out_isqrt[row]
// L2MODE:    result = acc * in_isqrt[v] + b2  (final output)
template <bool SCALE_SRC, bool L2MODE>
__global__ __launch_bounds__(256)
void k_agg_csr(const float* __restrict__ feat, float* __restrict__ outp,
               const float* __restrict__ b2) {
    int w = (blockIdx.x * blockDim.x + threadIdx.x) >> 5;
    int lane = threadIdx.x & 31;
    if (w >= N_NODES) return;
    const float4* f4 = reinterpret_cast<const float4*>(feat);
    float4 self = f4[(size_t)w * 32 + lane];
    float4 acc, acc2 = make_float4(0.f, 0.f, 0.f, 0.f);
    if (SCALE_SRC) {
        float ss = g_out_isqrt[w];
        acc = make_float4(self.x * ss, self.y * ss, self.z * ss, self.w * ss);
    } else {
        acc = self;
    }
    const int st = g_rowstart[w], cn = g_cnt_in[w];
    int j = 0;
    for (; j + 2 <= cn; j += 2) {
        int s0 = g_csrc[st + j], s1 = g_csrc[st + j + 1];
        float sc0 = SCALE_SRC ? g_out_isqrt[s0] : 1.f;
        float sc1 = SCALE_SRC ? g_out_isqrt[s1] : 1.f;
        float4 a0 = f4[(size_t)s0 * 32 + lane];
        float4 a1 = f4[(size_t)s1 * 32 + lane];
        if (SCALE_SRC) {
            acc.x = fmaf(a0.x, sc0, acc.x); acc.y = fmaf(a0.y, sc0, acc.y);
            acc.z = fmaf(a0.z, sc0, acc.z); acc.w = fmaf(a0.w, sc0, acc.w);
            acc2.x = fmaf(a1.x, sc1, acc2.x); acc2.y = fmaf(a1.y, sc1, acc2.y);
            acc2.z = fmaf(a1.z, sc1, acc2.z); acc2.w = fmaf(a1.w, sc1, acc2.w);
        } else {
            acc.x += a0.x; acc.y += a0.y; acc.z += a0.z; acc.w += a0.w;
            acc2.x += a1.x; acc2.y += a1.y; acc2.z += a1.z; acc2.w += a1.w;
        }
    }
    if (j < cn) {
        int s0 = g_csrc[st + j];
        float sc0 = SCALE_SRC ? g_out_isqrt[s0] : 1.f;
        float4 a0 = f4[(size_t)s0 * 32 + lane];
        if (SCALE_SRC) {
            acc.x = fmaf(a0.x, sc0, acc.x); acc.y = fmaf(a0.y, sc0, acc.y);
            acc.z = fmaf(a0.z, sc0, acc.z); acc.w = fmaf(a0.w, sc0, acc.w);
        } else {
            acc.x += a0.x; acc.y += a0.y; acc.z += a0.z; acc.w += a0.w;
        }
    }
    acc.x += acc2.x; acc.y += acc2.y; acc.z += acc2.z; acc.w += acc2.w;
    if (L2MODE) {
        float s = g_in_isqrt[w];
        float4 b = reinterpret_cast<const float4*>(b2)[lane];
        acc.x = fmaf(acc.x, s, b.x); acc.y = fmaf(acc.y, s, b.y);
        acc.z = fmaf(acc.z, s, b.z); acc.w = fmaf(acc.w, s, b.w);
    }
    reinterpret_cast<float4*>(outp)[(size_t)w * 32 + lane] = acc;
}

// ---------------- weight prep: split + transpose, [n][K+8] ----------------
__global__ void k_prep_B(const float* __restrict__ W, __nv_bfloat16* __restrict__ Bh,
                         __nv_bfloat16* __restrict__ Bl, int K, int Nc) {
    int idx = blockIdx.x * blockDim.x + threadIdx.x;
    if (idx >= K * Nc) return;
    int n = idx / K, k = idx % K;
    float w = W[(size_t)k * Nc + n];
    __nv_bfloat16 h = __float2bfloat16(w);
    __nv_bfloat16 l = __float2bfloat16(w - __bfloat162float(h));
    Bh[(size_t)n * (K + 8) + k] = h;
    Bl[(size_t)n * (K + 8) + k] = l;
}

__device__ __forceinline__ void pk2(float a, float b, float s, uint32_t& uh, uint32_t& ul) {
    a *= s; b *= s;
    __nv_bfloat16 ha = __float2bfloat16(a), hb = __float2bfloat16(b);
    __nv_bfloat16 la = __float2bfloat16(a - __bfloat162float(ha));
    __nv_bfloat16 lb = __float2bfloat16(b - __bfloat162float(hb));
    uh = (uint32_t)__bfloat16_as_ushort(ha) | ((uint32_t)__bfloat16_as_ushort(hb) << 16);
    ul = (uint32_t)__bfloat16_as_ushort(la) | ((uint32_t)__bfloat16_as_ushort(lb) << 16);
}

// ---------------- mma.sync bf16 split-GEMM, cp.async B + frag-reuse mma ----------------
template <int NC, int KSRC, bool L1MODE>
__global__ __launch_bounds__(256, 2)
void k_gemm_mma(const float* __restrict__ A, const __nv_bfloat16* __restrict__ Bh_img,
                const __nv_bfloat16* __restrict__ Bl_img, const float* __restrict__ prescale,
                const float* __restrict__ bias, const float* __restrict__ postscale,
                float* __restrict__ C) {
    constexpr int KPAD = KSRC + 8;
    constexpr int NCHUNK = KSRC / 64;
    constexpr uint32_t ROWB = 144;
    constexpr uint32_t SZ = 128 * ROWB;

    extern __shared__ char smem[];
    uint32_t sb;
    asm("{ .reg .u64 t; cvta.to.shared.u64 t, %1; cvt.u32.u64 %0, t; }" : "=r"(sb) : "l"(smem));
    const uint32_t sAh = sb, sAl = sb + SZ, sBh = sb + 2 * SZ, sBl = sb + 3 * SZ;

    const int tid = threadIdx.x, wid = tid >> 5, lane = tid & 31;
    const int wm = wid & 3, wn = wid >> 2;
    const int m0 = blockIdx.y * 128, n0 = blockIdx.x * 128;

    const int r = tid >> 1, cb = (tid & 1) * 32;
    const int arow = m0 + r;
    float s = 1.0f;
    if (L1MODE && arow < N_NODES) s = prescale[arow];

    const uint32_t a_off = (uint32_t)((wm * 32 + ((lane >> 3) & 1) * 8 + (lane & 7)) * ROWB
                                      + (lane >> 4) * 16);
    const uint32_t b_off = (uint32_t)((wn * 64 + ((lane >> 4) << 3) + (lane & 7)) * ROWB
                                      + ((lane >> 3) & 1) * 16);

    float acc[2][8][4] = {};

    for (int ch = 0; ch < NCHUNK; ch++) {
        if (ch) __syncthreads();   // previous chunk's ldmatrix done before smem overwrite
        // ---- B tiles via cp.async (latency hides under A-convert below) ----
        #pragma unroll
        for (int i = tid; i < 1024; i += 256) {
            int row = i >> 3, j = i & 7;
            uint32_t off = (uint32_t)(row * ROWB + j * 16);
            const __nv_bfloat16* ph = Bh_img + (size_t)(n0 + row) * KPAD + ch * 64 + j * 8;
            const __nv_bfloat16* pl = Bl_img + (size_t)(n0 + row) * KPAD + ch * 64 + j * 8;
            asm volatile("cp.async.cg.shared.global [%0], [%1], 16;"
                         :: "r"(sBh + off), "l"(ph));
            asm volatile("cp.async.cg.shared.global [%0], [%1], 16;"
                         :: "r"(sBl + off), "l"(pl));
        }
        asm volatile("cp.async.commit_group;");
        // ---- A convert: 128x64 f32 -> Ah/Al bf16 ----
        {
            float4 v[8];
            if (arow < N_NODES) {
                const float4* ap = reinterpret_cast<const float4*>(
                    A + (size_t)arow * KSRC + ch * 64 + cb);
                #pragma unroll
                for (int j = 0; j < 8; j++) v[j] = ap[j];
            } else {
                #pragma unroll
                for (int j = 0; j < 8; j++) v[j] = make_float4(0.f, 0.f, 0.f, 0.f);
            }
            #pragma unroll
            for (int j = 0; j < 4; j++) {
                float4 p = v[2 * j], q = v[2 * j + 1];
                uint32_t h0, l0, h1, l1, h2, l2, h3, l3;
                pk2(p.x, p.y, s, h0, l0); pk2(p.z, p.w, s, h1, l1);
                pk2(q.x, q.y, s, h2, l2); pk2(q.z, q.w, s, h3, l3);
                uint32_t off = (uint32_t)(r * ROWB + cb * 2 + j * 16);
                asm volatile("st.shared.v4.b32 [%0], {%1,%2,%3,%4};"
                             :: "r"(sAh + off), "r"(h0), "r"(h1), "r"(h2), "r"(h3));
                asm volatile("st.shared.v4.b32 [%0], {%1,%2,%3,%4};"
                             :: "r"(sAl + off), "r"(l0), "r"(l1), "r"(l2), "r"(l3));
            }
        }
        asm volatile("cp.async.wait_group 0;");
        __syncthreads();

        // ---- per k-step: load frags once, 3 mma sets ----
        #pragma unroll
        for (int ks = 0; ks < 4; ks++) {
            uint32_t bh[4][4], a0[2][4], a1[2][4];
            #pragma unroll
            for (int nj = 0; nj < 4; nj++)
                asm volatile(
                    "ldmatrix.sync.aligned.m8n8.x4.shared.b16 {%0,%1,%2,%3}, [%4];"
                    : "=r"(bh[nj][0]), "=r"(bh[nj][1]), "=r"(bh[nj][2]), "=r"(bh[nj][3])
                    : "r"(sBh + b_off + (uint32_t)(nj * 16 * ROWB + ks * 32)));
            #pragma unroll
            for (int mi = 0; mi < 2; mi++)
                asm volatile(
                    "ldmatrix.sync.aligned.m8n8.x4.shared.b16 {%0,%1,%2,%3}, [%4];"
                    : "=r"(a0[mi][0]), "=r"(a0[mi][1]), "=r"(a0[mi][2]), "=r"(a0[mi][3])
                    : "r"(sAh + a_off + (uint32_t)(mi * 16 * ROWB + ks * 32)));
            #pragma unroll
            for (int mi = 0; mi < 2; mi++)
                #pragma unroll
                for (int nj = 0; nj < 8; nj++) {
                    float* d = acc[mi][nj];
                    asm volatile(
                        "mma.sync.aligned.m16n8k16.row.col.f32.bf16.bf16.f32 "
                        "{%0,%1,%2,%3}, {%4,%5,%6,%7}, {%8,%9}, {%0,%1,%2,%3};"
                        : "+f"(d[0]), "+f"(d[1]), "+f"(d[2]), "+f"(d[3])
                        : "r"(a0[mi][0]), "r"(a0[mi][1]), "r"(a0[mi][2]), "r"(a0[mi][3]),
                          "r"(bh[nj >> 1][(nj & 1) * 2]), "r"(bh[nj >> 1][(nj & 1) * 2 + 1]));
                }
            #pragma unroll
            for (int mi = 0; mi < 2; mi++)
                asm volatile(
                    "ldmatrix.sync.aligned.m8n8.x4.shared.b16 {%0,%1,%2,%3}, [%4];"
                    : "=r"(a1[mi][0]), "=r"(a1[mi][1]), "=r"(a1[mi][2]), "=r"(a1[mi][3])
                    : "r"(sAl + a_off + (uint32_t)(mi * 16 * ROWB + ks * 32)));
            #pragma unroll
            for (int mi = 0; mi < 2; mi++)
                #pragma unroll
                for (int nj = 0; nj < 8; nj++) {
                    float* d = acc[mi][nj];
                    asm volatile(
                        "mma.sync.aligned.m16n8k16.row.col.f32.bf16.bf16.f32 "
                        "{%0,%1,%2,%3}, {%4,%5,%6,%7}, {%8,%9}, {%0,%1,%2,%3};"
                        : "+f"(d[0]), "+f"(d[1]), "+f"(d[2]), "+f"(d[3])
                        : "r"(a1[mi][0]), "r"(a1[mi][1]), "r"(a1[mi][2]), "r"(a1[mi][3]),
                          "r"(bh[nj >> 1][(nj & 1) * 2]), "r"(bh[nj >> 1][(nj & 1) * 2 + 1]));
                }
            #pragma unroll
            for (int nj = 0; nj < 4; nj++)   // reuse bh regs for Bl
                asm volatile(
                    "ldmatrix.sync.aligned.m8n8.x4.shared.b16 {%0,%1,%2,%3}, [%4];"
                    : "=r"(bh[nj][0]), "=r"(bh[nj][1]), "=r"(bh[nj][2]), "=r"(bh[nj][3])
                    : "r"(sBl + b_off + (uint32_t)(nj * 16 * ROWB + ks * 32)));
            #pragma unroll
            for (int mi = 0; mi < 2; mi++)
                #pragma unroll
                for (int nj = 0; nj < 8; nj++) {
                    float* d = acc[mi][nj];
                    asm volatile(
                        "mma.sync.aligned.m16n8k16.row.col.f32.bf16.bf16.f32 "
                        "{%0,%1,%2,%3}, {%4,%5,%6,%7}, {%8,%9}, {%0,%1,%2,%3};"
                        : "+f"(d[0]), "+f"(d[1]), "+f"(d[2]), "+f"(d[3])
                        : "r"(a0[mi][0]), "r"(a0[mi][1]), "r"(a0[mi][2]), "r"(a0[mi][3]),
                          "r"(bh[nj >> 1][(nj & 1) * 2]), "r"(bh[nj >> 1][(nj & 1) * 2 + 1]));
                }
        }
    }

    // ---- epilogue ----
    #pragma unroll
    for (int mi = 0; mi < 2; mi++) {
        int row0 = m0 + wm * 32 + mi * 16 + (lane >> 2);
        int row1 = row0 + 8;
        float os0 = 1.f, os1 = 1.f;
        if (L1MODE) {
            if (row0 < N_NODES) os0 = postscale[row0];
            if (row1 < N_NODES) os1 = postscale[row1];
        }
        #pragma unroll
        for (int nj = 0; nj < 8; nj++) {
            int col = n0 + wn * 64 + nj * 8 + (lane & 3) * 2;
            float* d = acc[mi][nj];
            float2 v0 = make_float2(d[0], d[1]);
            float2 v1 = make_float2(d[2], d[3]);
            if (L1MODE) {
                float2 bv = *reinterpret_cast<const float2*>(&bias[col]);
                v0.x = fmaxf(v0.x + bv.x, 0.f) * os0;
                v0.y = fmaxf(v0.y + bv.y, 0.f) * os0;
                v1.x = fmaxf(v1.x + bv.x, 0.f) * os1;
                v1.y = fmaxf(v1.y + bv.y, 0.f) * os1;
            }
            if (row0 < N_NODES)
                *reinterpret_cast<float2*>(&C[(size_t)row0 * NC + col]) = v0;
            if (row1 < N_NODES)
                *reinterpret_cast<float2*>(&C[(size_t)row1 * NC + col]) = v1;
        }
    }
}

extern "C" void kernel_launch(void* const* d_in, const int* in_sizes, int n_in,
                              void* d_out, int out_size) {
    const float* x  = (const float*)d_in[0];
    const int*   ei = (const int*)d_in[1];
    const float* W1 = (const float*)d_in[2];
    const float* b1 = (const float*)d_in[3];
    const float* W2 = (const float*)d_in[4];
    const float* b2 = (const float*)d_in[5];
    float* out = (float*)d_out;

    float *m1, *t1, *gg, *in_isqrt, *out_isqrt;
    __nv_bfloat16 *b1h, *b1l, *b2h, *b2l;
    cudaGetSymbolAddress((void**)&m1, g_m1);
    cudaGetSymbolAddress((void**)&t1, g_t1);
    cudaGetSymbolAddress((void**)&gg, g_g);
    cudaGetSymbolAddress((void**)&in_isqrt, g_in_isqrt);
    cudaGetSymbolAddress((void**)&out_isqrt, g_out_isqrt);
    cudaGetSymbolAddress((void**)&b1h, g_B1h);
    cudaGetSymbolAddress((void**)&b1l, g_B1l);
    cudaGetSymbolAddress((void**)&b2h, g_B2h);
    cudaGetSymbolAddress((void**)&b2l, g_B2l);

    static bool attr_set = false;
    if (!attr_set) {
        cudaFuncSetAttribute(k_gemm_mma<HID_F, IN_F, true>,
                             cudaFuncAttributeMaxDynamicSharedMemorySize, 73728);
        cudaFuncSetAttribute(k_gemm_mma<OUT_F, HID_F, false>,
                             cudaFuncAttributeMaxDynamicSharedMemorySize, 73728);
        attr_set = true;
    }

    // ---- CSR build + degrees ----
    k_hist_init<<<(N_NODES + 255) / 256, 256>>>();
    k_hist<<<(E_EDGES + 255) / 256, 256>>>(ei);
    k_scanA<<<NB_SCAN, 256>>>();
    k_scanB<<<1, 256>>>();
    k_scanC<<<(N_NODES + 255) / 256, 256>>>();
    k_scatter<<<(E_EDGES + 255) / 256, 256>>>(ei);

    // ---- weight prep ----
    k_prep_B<<<(IN_F * HID_F + 255) / 256, 256>>>(W1, b1h, b1l, IN_F, HID_F);
    k_prep_B<<<(HID_F * OUT_F + 255) / 256, 256>>>(W2, b2h, b2l, HID_F, OUT_F);

    // ---- layer 1: fused-scale gather (reads x directly) ----
    k_agg_csr<true, false><<<(N_NODES * 32 + 255) / 256, 256>>>(x, m1, nullptr);
    {
        dim3 grid(HID_F / 128, (N_NODES + 127) / 128);
        k_gemm_mma<HID_F, IN_F, true><<<grid, 256, 73728>>>(
            m1, b1h, b1l, in_isqrt, b1, out_isqrt, t1);
    }
    // ---- layer 2 ----
    {
        dim3 grid(OUT_F / 128, (N_NODES + 127) / 128);
        k_gemm_mma<OUT_F, HID_F, false><<<grid, 256, 73728>>>(
            t1, b2h, b2l, nullptr, nullptr, nullptr, gg);
    }
    k_agg_csr<false, true><<<(N_NODES * 32 + 255) / 256, 256>>>(gg, out, b2);
}